// round 4
// baseline (speedup 1.0000x reference)
#include <cuda_runtime.h>
#include <math.h>

// Problem constants
#define BB 4
#define NN 2048
#define DIM 512
#define HEADS 8
#define DH 64
#define HIDDEN 512          // HEADS*DH
#define THC 1536            // 3*HIDDEN

// ---------------- scratch (device globals: allocation-free rule) ----------
__device__ float g_qkv[(size_t)BB * NN * THC];        // 48 MB
__device__ float g_q  [(size_t)BB * HEADS * NN * DH]; // 16 MB
__device__ float g_k  [(size_t)BB * HEADS * NN * DH]; // 16 MB
__device__ float g_v  [(size_t)BB * HEADS * NN * DH]; // 16 MB
__device__ float g_mid[(size_t)BB * NN * HIDDEN];     // 16 MB

// inv_freq[i] = 10000^(-2i/64) = 10^(-i/8), correctly-rounded fp32
__constant__ float c_invfreq[32] = {
    1.0f,
    0.74989420933245582f, 0.56234132519034907f, 0.42169650342858220f,
    0.31622776601683794f, 0.23713737056616552f, 0.17782794100389228f,
    0.13335214321633240f, 0.1f,
    0.074989420933245582f, 0.056234132519034907f, 0.042169650342858220f,
    0.031622776601683794f, 0.023713737056616552f, 0.017782794100389228f,
    0.013335214321633240f, 0.01f,
    0.0074989420933245582f, 0.0056234132519034907f, 0.0042169650342858220f,
    0.0031622776601683794f, 0.0023713737056616552f, 0.0017782794100389228f,
    0.0013335214321633240f, 0.001f,
    0.00074989420933245582f, 0.00056234132519034907f, 0.00042169650342858220f,
    0.00031622776601683794f, 0.00023713737056616552f, 0.00017782794100389228f,
    0.00013335214321633240f
};

// =====================================================================
// SGEMM: C[M,Nc] = A[M,K] @ B[K,Nc], all row-major fp32.
// 64x64 tile, BK=16, 256 threads, 4x4 register tile per thread.
// A tile stored k-major (transposed) with stride 68 for float4 loads.
// =====================================================================
__global__ __launch_bounds__(256)
void sgemm64(const float* __restrict__ A, const float* __restrict__ Bm,
             float* __restrict__ C, int M, int Nc, int K)
{
    __shared__ float Ast[16 * 68];   // [k][m], stride 68
    __shared__ float Bs [16 * 64];   // [k][n]

    const int tid = threadIdx.x;
    const int tx  = tid & 15;
    const int ty  = tid >> 4;
    const int m0  = blockIdx.y * 64;
    const int n0  = blockIdx.x * 64;

    float acc[4][4];
#pragma unroll
    for (int i = 0; i < 4; ++i)
#pragma unroll
        for (int j = 0; j < 4; ++j) acc[i][j] = 0.f;

    const int ar  = tid >> 2;          // 0..63 (row within A tile)
    const int ak4 = (tid & 3) * 4;     // 0,4,8,12
    const int bk  = tid >> 4;          // 0..15
    const int bc4 = (tid & 15) * 4;    // 0..60

    for (int k0 = 0; k0 < K; k0 += 16) {
        // A tile -> Ast transposed
        float4 av = *(const float4*)&A[(size_t)(m0 + ar) * K + k0 + ak4];
        Ast[(ak4 + 0) * 68 + ar] = av.x;
        Ast[(ak4 + 1) * 68 + ar] = av.y;
        Ast[(ak4 + 2) * 68 + ar] = av.z;
        Ast[(ak4 + 3) * 68 + ar] = av.w;
        // B tile -> Bs row-major
        *(float4*)&Bs[bk * 64 + bc4] =
            *(const float4*)&Bm[(size_t)(k0 + bk) * Nc + n0 + bc4];
        __syncthreads();

#pragma unroll
        for (int k = 0; k < 16; ++k) {
            float4 a = *(const float4*)&Ast[k * 68 + (ty << 2)];
            float4 b = *(const float4*)&Bs [k * 64 + (tx << 2)];
            acc[0][0] += a.x * b.x; acc[0][1] += a.x * b.y; acc[0][2] += a.x * b.z; acc[0][3] += a.x * b.w;
            acc[1][0] += a.y * b.x; acc[1][1] += a.y * b.y; acc[1][2] += a.y * b.z; acc[1][3] += a.y * b.w;
            acc[2][0] += a.z * b.x; acc[2][1] += a.z * b.y; acc[2][2] += a.z * b.z; acc[2][3] += a.z * b.w;
            acc[3][0] += a.w * b.x; acc[3][1] += a.w * b.y; acc[3][2] += a.w * b.z; acc[3][3] += a.w * b.w;
        }
        __syncthreads();
    }

#pragma unroll
    for (int i = 0; i < 4; ++i) {
        float4 o = make_float4(acc[i][0], acc[i][1], acc[i][2], acc[i][3]);
        *(float4*)&C[(size_t)(m0 + (ty << 2) + i) * Nc + n0 + (tx << 2)] = o;
    }
}

// =====================================================================
// QKV split + head reshape + rotary (+ q scale). One thread per
// (b,h,n,pair); pair covers dims (2i, 2i+1).
// =====================================================================
__global__ __launch_bounds__(256)
void qkv_transform()
{
    const int idx  = blockIdx.x * 256 + threadIdx.x;   // B*H*N*32 threads
    const int pair = idx & 31;
    const int n    = (idx >> 5) & (NN - 1);
    const int bh   = idx >> 16;                        // b*HEADS + h
    const int b    = bh >> 3;
    const int h    = bh & 7;

    const float* src = g_qkv + (size_t)(b * NN + n) * THC;
    const int col = h * DH + pair * 2;

    float2 qv = *(const float2*)&src[col];
    float2 kv = *(const float2*)&src[HIDDEN + col];
    float2 vv = *(const float2*)&src[2 * HIDDEN + col];

    float fr = (float)n * c_invfreq[pair];
    float sn, cs;
    sincosf(fr, &sn, &cs);

    const float scale = 0.125f;   // DH^-0.5
    float oq0 = (qv.x * cs - qv.y * sn) * scale;
    float oq1 = (qv.y * cs + qv.x * sn) * scale;
    float ok0 = kv.x * cs - kv.y * sn;
    float ok1 = kv.y * cs + kv.x * sn;

    size_t o = ((size_t)bh * NN + n) * DH + pair * 2;
    g_q[o] = oq0; g_q[o + 1] = oq1;
    g_k[o] = ok0; g_k[o + 1] = ok1;
    g_v[o] = vv.x; g_v[o + 1] = vv.y;
}

// =====================================================================
// Fused flash attention, fp32.
// grid = (N/64, HEADS, B), block = 256 threads (16x16 logical).
// Q tile 64 rows, key tiles of 32. Thread computes S 4x2, O 4x4.
// smem: Qt[d][r] s68, Kt[d][c] s36, Vs[kk][c] s68, Pst[kk][r] s68.
// Total 44032 B (static, < 48KB).
// =====================================================================
__global__ __launch_bounds__(256)
void attn_kernel(const float* __restrict__ bias)
{
    __shared__ float Qt [64 * 68];
    __shared__ float Kt [64 * 36];
    __shared__ float Vs [32 * 68];
    __shared__ float Pst[32 * 68];

    const int tid = threadIdx.x;
    const int tx  = tid & 15;
    const int ty  = tid >> 4;
    const int q0  = blockIdx.x * 64;
    const int h   = blockIdx.y;
    const int b   = blockIdx.z;
    const size_t base = ((size_t)(b * HEADS + h)) * NN * DH;
    const float* biash = bias + (size_t)h * NN * NN;

    // load Q tile transposed: Qt[d][r]
#pragma unroll
    for (int i = tid; i < 64 * 16; i += 256) {
        int r  = i >> 4;
        int d4 = (i & 15) * 4;
        float4 t = *(const float4*)&g_q[base + (size_t)(q0 + r) * DH + d4];
        Qt[(d4 + 0) * 68 + r] = t.x;
        Qt[(d4 + 1) * 68 + r] = t.y;
        Qt[(d4 + 2) * 68 + r] = t.z;
        Qt[(d4 + 3) * 68 + r] = t.w;
    }

    float m_i[4], l_i[4], O[4][4];
#pragma unroll
    for (int i = 0; i < 4; ++i) {
        m_i[i] = -INFINITY; l_i[i] = 0.f;
#pragma unroll
        for (int j = 0; j < 4; ++j) O[i][j] = 0.f;
    }

    for (int j0 = 0; j0 < NN; j0 += 32) {
        __syncthreads();   // prior PV-phase reads of Kt/Vs/Pst complete

        // K tile transposed: Kt[d][c], c in 0..31
#pragma unroll
        for (int i = tid; i < 32 * 16; i += 256) {
            int c  = i >> 4;
            int d4 = (i & 15) * 4;
            float4 t = *(const float4*)&g_k[base + (size_t)(j0 + c) * DH + d4];
            Kt[(d4 + 0) * 36 + c] = t.x;
            Kt[(d4 + 1) * 36 + c] = t.y;
            Kt[(d4 + 2) * 36 + c] = t.z;
            Kt[(d4 + 3) * 36 + c] = t.w;
        }
        // V tile row-major: Vs[kk][c]
#pragma unroll
        for (int i = tid; i < 32 * 16; i += 256) {
            int r  = i >> 4;
            int d4 = (i & 15) * 4;
            *(float4*)&Vs[r * 68 + d4] =
                *(const float4*)&g_v[base + (size_t)(j0 + r) * DH + d4];
        }
        __syncthreads();

        // ---- S = Q K^T + bias  (4 rows x 2 cols per thread) ----
        float S[4][2];
#pragma unroll
        for (int i = 0; i < 4; ++i) {
            float2 bb = *(const float2*)
                &biash[(size_t)(q0 + (ty << 2) + i) * NN + j0 + (tx << 1)];
            S[i][0] = bb.x; S[i][1] = bb.y;
        }
#pragma unroll 8
        for (int d = 0; d < 64; ++d) {
            float4 a = *(const float4*)&Qt[d * 68 + (ty << 2)];
            float2 bq = *(const float2*)&Kt[d * 36 + (tx << 1)];
            S[0][0] += a.x * bq.x; S[0][1] += a.x * bq.y;
            S[1][0] += a.y * bq.x; S[1][1] += a.y * bq.y;
            S[2][0] += a.z * bq.x; S[2][1] += a.z * bq.y;
            S[3][0] += a.w * bq.x; S[3][1] += a.w * bq.y;
        }

        // ---- online softmax (row reductions across tx via width-16 shfl) --
#pragma unroll
        for (int i = 0; i < 4; ++i) {
            float tm = fmaxf(S[i][0], S[i][1]);
#pragma unroll
            for (int off = 8; off >= 1; off >>= 1)
                tm = fmaxf(tm, __shfl_xor_sync(0xffffffffu, tm, off, 16));
            float mn = fmaxf(m_i[i], tm);
            float al = __expf(m_i[i] - mn);
            m_i[i] = mn;
            float p0 = __expf(S[i][0] - mn);
            float p1 = __expf(S[i][1] - mn);
            float ts = p0 + p1;
#pragma unroll
            for (int off = 8; off >= 1; off >>= 1)
                ts += __shfl_xor_sync(0xffffffffu, ts, off, 16);
            l_i[i] = l_i[i] * al + ts;
#pragma unroll
            for (int j = 0; j < 4; ++j) O[i][j] *= al;
            // store P transposed: Pst[kk][r]
            Pst[((tx << 1) + 0) * 68 + (ty << 2) + i] = p0;
            Pst[((tx << 1) + 1) * 68 + (ty << 2) + i] = p1;
        }
        __syncthreads();

        // ---- O += P @ V ----
#pragma unroll 8
        for (int kk = 0; kk < 32; ++kk) {
            float4 a = *(const float4*)&Pst[kk * 68 + (ty << 2)];
            float4 v = *(const float4*)&Vs [kk * 68 + (tx << 2)];
            O[0][0] += a.x * v.x; O[0][1] += a.x * v.y; O[0][2] += a.x * v.z; O[0][3] += a.x * v.w;
            O[1][0] += a.y * v.x; O[1][1] += a.y * v.y; O[1][2] += a.y * v.z; O[1][3] += a.y * v.w;
            O[2][0] += a.z * v.x; O[2][1] += a.z * v.y; O[2][2] += a.z * v.z; O[2][3] += a.z * v.w;
            O[3][0] += a.w * v.x; O[3][1] += a.w * v.y; O[3][2] += a.w * v.z; O[3][3] += a.w * v.w;
        }
    }

    // ---- finalize: /l and write to [b, n, h*64 + c] for the output GEMM ----
#pragma unroll
    for (int i = 0; i < 4; ++i) {
        float inv = 1.f / l_i[i];
        float4 o = make_float4(O[i][0] * inv, O[i][1] * inv,
                               O[i][2] * inv, O[i][3] * inv);
        *(float4*)&g_mid[(size_t)(b * NN + q0 + (ty << 2) + i) * HIDDEN
                         + h * DH + (tx << 2)] = o;
    }
}

// =====================================================================
extern "C" void kernel_launch(void* const* d_in, const int* in_sizes, int n_in,
                              void* d_out, int out_size)
{
    const float *x = nullptr, *bias = nullptr, *wqkv = nullptr, *wout = nullptr;
    for (int i = 0; i < n_in; ++i) {
        switch (in_sizes[i]) {
            case 4194304:  x    = (const float*)d_in[i]; break;  // x [4,2048,512]
            case 33554432: bias = (const float*)d_in[i]; break;  // pos_bias [8,2048,2048]
            case 786432:   wqkv = (const float*)d_in[i]; break;  // W_qkv [512,1536]
            case 262144:   wout = (const float*)d_in[i]; break;  // W_out [512,512]
        }
    }

    void *p_qkv = nullptr, *p_mid = nullptr;
    cudaGetSymbolAddress(&p_qkv, g_qkv);
    cudaGetSymbolAddress(&p_mid, g_mid);

    // 1) qkv = x @ W_qkv
    sgemm64<<<dim3(THC / 64, (BB * NN) / 64), 256>>>(
        x, wqkv, (float*)p_qkv, BB * NN, THC, DIM);

    // 2) split + rotary + scale
    qkv_transform<<<(BB * HEADS * NN * 32) / 256, 256>>>();

    // 3) fused flash attention (+pos_bias, softmax)
    attn_kernel<<<dim3(NN / 64, HEADS, BB), 256>>>(bias);

    // 4) out = mid @ W_out
    sgemm64<<<dim3(DIM / 64, (BB * NN) / 64), 256>>>(
        (const float*)p_mid, wout, (float*)d_out, BB * NN, DIM, HIDDEN);
}